// round 1
// baseline (speedup 1.0000x reference)
#include <cuda_runtime.h>
#include <cuda_bf16.h>

// Problem constants
#define BSZ   32
#define SSZ   1024
#define DSZ   768
#define HSZ   128
#define RSZ   48
#define APP   (SSZ + 1)        // 1025 (root-appended sequence length)
#define NTOK  (BSZ * SSZ)      // 32768
#define MHEAD (BSZ * APP)      // 32800

// Scratch (device globals: allocation-free per harness rules)
__device__ float g_head[(size_t)MHEAD * HSZ];   // relu(appended @ Wh + bh), all positions
__device__ float g_tail[(size_t)NTOK * HSZ];    // relu(x @ Wt + bt)

// ---------------------------------------------------------------------------
// Kernel 1: dual feed-forward GEMM.
//   branch 0: head_all[m, :] = relu(appended_row(m) @ Wh + bh), m in [0, 32800)
//   branch 1: tail[m, :]     = relu(x[m, :] @ Wt + bt),         m in [0, 32768)
// Tile: 128(M) x 128(N=H), K-chunk 32. 256 threads, 8x8 micro-tile per thread.
// ---------------------------------------------------------------------------
__global__ __launch_bounds__(256) void ff_kernel(
    const float* __restrict__ x,
    const float* __restrict__ root,
    const float* __restrict__ Wh, const float* __restrict__ bh,
    const float* __restrict__ Wt, const float* __restrict__ bt)
{
    const int branch = blockIdx.y;
    const int M      = (branch == 0) ? MHEAD : NTOK;
    const int m0     = blockIdx.x * 128;
    if (m0 >= M) return;

    const float* W    = (branch == 0) ? Wh : Wt;
    const float* bias = (branch == 0) ? bh : bt;
    float*       outp = (branch == 0) ? g_head : g_tail;

    __shared__ float As[32][128];   // As[k][m] (transposed A tile)
    __shared__ float Bs[32][128];   // Bs[k][n]

    const int tid = threadIdx.x;
    const int tx  = tid & 15;       // 0..15 -> N
    const int ty  = tid >> 4;       // 0..15 -> M

    // Precompute per-row source pointers for the 4 A-tile rows this thread loads.
    const float* arow[4];
    bool rowok[4];
#pragma unroll
    for (int i = 0; i < 4; i++) {
        int f4  = tid + i * 256;
        int row = f4 >> 3;          // 0..127 row within tile (8 float4 per row)
        int g   = m0 + row;
        const float* p = nullptr;
        bool ok = (g < M);
        if (ok) {
            if (branch == 0) {
                int b  = g / APP;
                int ii = g - b * APP;   // 0 -> root, else x[b, ii-1]
                p = (ii == 0) ? root : (x + (size_t)(b * SSZ + (ii - 1)) * DSZ);
            } else {
                p = x + (size_t)g * DSZ;
            }
        }
        arow[i] = p;
        rowok[i] = ok;
    }

    float acc[8][8];
#pragma unroll
    for (int i = 0; i < 8; i++)
#pragma unroll
        for (int j = 0; j < 8; j++) acc[i][j] = 0.f;

    for (int k0 = 0; k0 < DSZ; k0 += 32) {
        // A tile (gathered rows), stored transposed As[k][m]
#pragma unroll
        for (int i = 0; i < 4; i++) {
            int f4  = tid + i * 256;
            int row = f4 >> 3;
            int c4  = f4 & 7;
            float4 v = make_float4(0.f, 0.f, 0.f, 0.f);
            if (rowok[i]) v = *(const float4*)(arow[i] + k0 + c4 * 4);
            As[c4 * 4 + 0][row] = v.x;
            As[c4 * 4 + 1][row] = v.y;
            As[c4 * 4 + 2][row] = v.z;
            As[c4 * 4 + 3][row] = v.w;
        }
        // B tile: W rows k0..k0+31, all 128 cols
#pragma unroll
        for (int i = 0; i < 4; i++) {
            int f4  = tid + i * 256;
            int row = f4 >> 5;      // 0..31
            int c4  = f4 & 31;
            *(float4*)&Bs[row][c4 * 4] =
                *(const float4*)(W + (size_t)(k0 + row) * HSZ + c4 * 4);
        }
        __syncthreads();

#pragma unroll
        for (int k = 0; k < 32; k++) {
            float a[8], b[8];
            *(float4*)&a[0] = *(float4*)&As[k][ty * 8];
            *(float4*)&a[4] = *(float4*)&As[k][ty * 8 + 4];
            *(float4*)&b[0] = *(float4*)&Bs[k][tx * 8];
            *(float4*)&b[4] = *(float4*)&Bs[k][tx * 8 + 4];
#pragma unroll
            for (int i = 0; i < 8; i++)
#pragma unroll
                for (int j = 0; j < 8; j++) acc[i][j] += a[i] * b[j];
        }
        __syncthreads();
    }

    // Epilogue: bias + relu + store
    float bv[8];
#pragma unroll
    for (int j = 0; j < 8; j++) bv[j] = bias[tx * 8 + j];
#pragma unroll
    for (int i = 0; i < 8; i++) {
        int row = m0 + ty * 8 + i;
        if (row < M) {
            float o[8];
#pragma unroll
            for (int j = 0; j < 8; j++) o[j] = fmaxf(acc[i][j] + bv[j], 0.f);
            *(float4*)&outp[(size_t)row * HSZ + tx * 8]     = *(float4*)&o[0];
            *(float4*)&outp[(size_t)row * HSZ + tx * 8 + 4] = *(float4*)&o[4];
        }
    }
}

// ---------------------------------------------------------------------------
// Kernel 2: biaffine. Block = 64 tokens x one r.
//   C[t,k] = sum_h head[t,h] * K[h, r*128 + k]   (64x128 GEMM, inner 128)
//   out[t,r] = sum_k C[t,k] * tail[t,k]          (fused epilogue)
// head rows gathered from g_head via head_id.
// smem: Hs 64x128 + Ts 64x128 + Kc 32x128 = 80 KB (dynamic).
// ---------------------------------------------------------------------------
__global__ __launch_bounds__(256) void biaffine_kernel(
    const int* __restrict__ head_id,
    const float* __restrict__ Kmat,     // (128, 6144) = (h, r*128 + k)
    float* __restrict__ out)            // (32768, 48)
{
    extern __shared__ float smem[];
    float* Hs = smem;                   // [64][128]
    float* Ts = smem + 64 * 128;        // [64][128]
    float* Kc = smem + 2 * 64 * 128;    // [32][128]

    const int t0  = blockIdx.x * 64;
    const int r   = blockIdx.y;
    const int tid = threadIdx.x;
    const int tx  = tid & 15;           // k direction
    const int ty  = tid >> 4;           // token direction

    // Load head (gathered) and tail tiles: 2048 float4 each, 8 per thread.
#pragma unroll
    for (int i = 0; i < 8; i++) {
        int f4  = tid + i * 256;
        int row = f4 >> 5;              // 0..63
        int c4  = f4 & 31;
        int t   = t0 + row;
        *(float4*)&Ts[row * 128 + c4 * 4] =
            *(const float4*)&g_tail[(size_t)t * HSZ + c4 * 4];
        int hid = head_id[t];
        int b   = t >> 10;
        const float* hp = &g_head[((size_t)b * APP + hid) * HSZ];
        *(float4*)&Hs[row * 128 + c4 * 4] = *(const float4*)&hp[c4 * 4];
    }

    float acc[4][8];
#pragma unroll
    for (int i = 0; i < 4; i++)
#pragma unroll
        for (int j = 0; j < 8; j++) acc[i][j] = 0.f;

    const float* Kr = Kmat + (size_t)r * HSZ;   // column block for this r

    for (int h0 = 0; h0 < HSZ; h0 += 32) {
        // Load K chunk: rows h0..h0+31, 128 cols (row stride 6144 in gmem)
#pragma unroll
        for (int i = 0; i < 4; i++) {
            int f4  = tid + i * 256;
            int row = f4 >> 5;          // 0..31
            int c4  = f4 & 31;
            *(float4*)&Kc[row * 128 + c4 * 4] =
                *(const float4*)(Kr + (size_t)(h0 + row) * (HSZ * RSZ) + c4 * 4);
        }
        __syncthreads();

#pragma unroll
        for (int h = 0; h < 32; h++) {
            float a[4];
#pragma unroll
            for (int i = 0; i < 4; i++) a[i] = Hs[(ty * 4 + i) * 128 + h0 + h];
            float b[8];
            *(float4*)&b[0] = *(float4*)&Kc[h * 128 + tx * 8];
            *(float4*)&b[4] = *(float4*)&Kc[h * 128 + tx * 8 + 4];
#pragma unroll
            for (int i = 0; i < 4; i++)
#pragma unroll
                for (int j = 0; j < 8; j++) acc[i][j] += a[i] * b[j];
        }
        __syncthreads();
    }

    // Fused contraction with tail + half-warp reduction over k (tx lanes)
#pragma unroll
    for (int i = 0; i < 4; i++) {
        float tb[8];
        *(float4*)&tb[0] = *(float4*)&Ts[(ty * 4 + i) * 128 + tx * 8];
        *(float4*)&tb[4] = *(float4*)&Ts[(ty * 4 + i) * 128 + tx * 8 + 4];
        float p = 0.f;
#pragma unroll
        for (int j = 0; j < 8; j++) p += acc[i][j] * tb[j];
#pragma unroll
        for (int o = 8; o > 0; o >>= 1)
            p += __shfl_down_sync(0xffffffffu, p, o, 16);
        if (tx == 0)
            out[(size_t)(t0 + ty * 4 + i) * RSZ + r] = p;
    }
}

// ---------------------------------------------------------------------------
extern "C" void kernel_launch(void* const* d_in, const int* in_sizes, int n_in,
                              void* d_out, int out_size)
{
    const float* x       = (const float*)d_in[0];
    const int*   head_id = (const int*)  d_in[1];
    const float* root    = (const float*)d_in[2];
    const float* Wh      = (const float*)d_in[3];
    const float* bh      = (const float*)d_in[4];
    const float* Wt      = (const float*)d_in[5];
    const float* bt      = (const float*)d_in[6];
    const float* Kmat    = (const float*)d_in[7];
    float*       out     = (float*)d_out;

    // Stage 1: dual FF GEMMs (branch 0: head over 32800 appended rows; branch 1: tail)
    ff_kernel<<<dim3(257, 2), 256>>>(x, root, Wh, bh, Wt, bt);

    // Stage 2: fused biaffine (gather + GEMM + contraction)
    const int smem_bytes = (2 * 64 * 128 + 32 * 128) * sizeof(float);  // 80 KB
    cudaFuncSetAttribute(biaffine_kernel,
                         cudaFuncAttributeMaxDynamicSharedMemorySize, smem_bytes);
    biaffine_kernel<<<dim3(NTOK / 64, RSZ), 256, smem_bytes>>>(head_id, Kmat, out);
}

// round 3
// speedup vs baseline: 2.1964x; 2.1964x over previous
#include <cuda_runtime.h>
#include <cuda_bf16.h>
#include <cstdint>

// Problem constants
#define BSZ   32
#define SSZ   1024
#define DSZ   768
#define HSZ   128
#define RSZ   48
#define APP   (SSZ + 1)        // 1025
#define NTOK  (BSZ * SSZ)      // 32768
#define MHEAD (BSZ * APP)      // 32800

// Scratch (device globals)
__device__ __nv_bfloat16 g_headH[(size_t)MHEAD * HSZ];   // hi bf16 of relu head
__device__ __nv_bfloat16 g_headL[(size_t)MHEAD * HSZ];   // lo residual bf16
__device__ float         g_tail [(size_t)NTOK * HSZ];    // fp32 tail
__device__ __nv_bfloat16 g_KH[(size_t)RSZ * HSZ * HSZ];  // B_r[n][h] hi
__device__ __nv_bfloat16 g_KL[(size_t)RSZ * HSZ * HSZ];  // B_r[n][h] lo

// ---------------------------------------------------------------------------
// PTX helpers (all target-suffix-free: valid for compute_103)
// ---------------------------------------------------------------------------
__device__ __forceinline__ uint32_t smem_u32(const void* p) {
    uint32_t a;
    asm("{ .reg .u64 t; cvta.to.shared.u64 t, %1; cvt.u32.u64 %0, t; }" : "=r"(a) : "l"(p));
    return a;
}

#define CP16(dst, src) \
    asm volatile("cp.async.cg.shared.global [%0], [%1], 16;" :: "r"(dst), "l"(src) : "memory")
#define CP_COMMIT() asm volatile("cp.async.commit_group;" ::: "memory")
#define CP_WAIT0()  asm volatile("cp.async.wait_group 0;" ::: "memory")

#define LDMX4(r, addr) \
    asm volatile("ldmatrix.sync.aligned.m8n8.x4.shared.b16 {%0,%1,%2,%3}, [%4];" \
        : "=r"((r)[0]), "=r"((r)[1]), "=r"((r)[2]), "=r"((r)[3]) : "r"(addr))

#define MMA16816(c, a, b0, b1) \
    asm volatile("mma.sync.aligned.m16n8k16.row.col.f32.bf16.bf16.f32 " \
        "{%0,%1,%2,%3}, {%4,%5,%6,%7}, {%8,%9}, {%0,%1,%2,%3};" \
        : "+f"((c)[0]), "+f"((c)[1]), "+f"((c)[2]), "+f"((c)[3]) \
        : "r"((a)[0]), "r"((a)[1]), "r"((a)[2]), "r"((a)[3]), "r"(b0), "r"(b1))

// ---------------------------------------------------------------------------
// Kernel 0: prep — transpose + bf16 hi/lo split of K into per-r [n][h] images.
// ---------------------------------------------------------------------------
__global__ void prep_kernel(const float* __restrict__ Kmat)
{
    const int r = blockIdx.x;
    for (int idx = threadIdx.x; idx < HSZ * HSZ; idx += blockDim.x) {
        int k = idx >> 7;          // h index (contraction dim)
        int n = idx & 127;         // output-k index
        float v = Kmat[(size_t)k * (HSZ * RSZ) + r * HSZ + n];
        __nv_bfloat16 hi = __float2bfloat16(v);
        __nv_bfloat16 lo = __float2bfloat16(v - __bfloat162float(hi));
        size_t off = (size_t)r * HSZ * HSZ + (size_t)n * HSZ + k;
        g_KH[off] = hi;
        g_KL[off] = lo;
    }
}

// ---------------------------------------------------------------------------
// Kernel 1: dual feed-forward GEMM (fp32). Branch 0 emits bf16 hi/lo head.
// ---------------------------------------------------------------------------
__global__ __launch_bounds__(256) void ff_kernel(
    const float* __restrict__ x,
    const float* __restrict__ root,
    const float* __restrict__ Wh, const float* __restrict__ bh,
    const float* __restrict__ Wt, const float* __restrict__ bt)
{
    const int branch = blockIdx.y;
    const int M      = (branch == 0) ? MHEAD : NTOK;
    const int m0     = blockIdx.x * 128;
    if (m0 >= M) return;

    const float* W    = (branch == 0) ? Wh : Wt;
    const float* bias = (branch == 0) ? bh : bt;

    __shared__ float As[32][128];
    __shared__ float Bs[32][128];

    const int tid = threadIdx.x;
    const int tx  = tid & 15;
    const int ty  = tid >> 4;

    const float* arow[4];
    bool rowok[4];
#pragma unroll
    for (int i = 0; i < 4; i++) {
        int f4  = tid + i * 256;
        int row = f4 >> 3;
        int g   = m0 + row;
        const float* p = nullptr;
        bool ok = (g < M);
        if (ok) {
            if (branch == 0) {
                int b  = g / APP;
                int ii = g - b * APP;
                p = (ii == 0) ? root : (x + (size_t)(b * SSZ + (ii - 1)) * DSZ);
            } else {
                p = x + (size_t)g * DSZ;
            }
        }
        arow[i] = p; rowok[i] = ok;
    }

    float acc[8][8];
#pragma unroll
    for (int i = 0; i < 8; i++)
#pragma unroll
        for (int j = 0; j < 8; j++) acc[i][j] = 0.f;

    for (int k0 = 0; k0 < DSZ; k0 += 32) {
#pragma unroll
        for (int i = 0; i < 4; i++) {
            int f4  = tid + i * 256;
            int row = f4 >> 3;
            int c4  = f4 & 7;
            float4 v = make_float4(0.f, 0.f, 0.f, 0.f);
            if (rowok[i]) v = *(const float4*)(arow[i] + k0 + c4 * 4);
            As[c4 * 4 + 0][row] = v.x;
            As[c4 * 4 + 1][row] = v.y;
            As[c4 * 4 + 2][row] = v.z;
            As[c4 * 4 + 3][row] = v.w;
        }
#pragma unroll
        for (int i = 0; i < 4; i++) {
            int f4  = tid + i * 256;
            int row = f4 >> 5;
            int c4  = f4 & 31;
            *(float4*)&Bs[row][c4 * 4] =
                *(const float4*)(W + (size_t)(k0 + row) * HSZ + c4 * 4);
        }
        __syncthreads();

#pragma unroll
        for (int k = 0; k < 32; k++) {
            float a[8], b[8];
            *(float4*)&a[0] = *(float4*)&As[k][ty * 8];
            *(float4*)&a[4] = *(float4*)&As[k][ty * 8 + 4];
            *(float4*)&b[0] = *(float4*)&Bs[k][tx * 8];
            *(float4*)&b[4] = *(float4*)&Bs[k][tx * 8 + 4];
#pragma unroll
            for (int i = 0; i < 8; i++)
#pragma unroll
                for (int j = 0; j < 8; j++) acc[i][j] += a[i] * b[j];
        }
        __syncthreads();
    }

    float bv[8];
#pragma unroll
    for (int j = 0; j < 8; j++) bv[j] = bias[tx * 8 + j];
#pragma unroll
    for (int i = 0; i < 8; i++) {
        int row = m0 + ty * 8 + i;
        if (row < M) {
            if (branch == 0) {
                __nv_bfloat16 hi8[8], lo8[8];
#pragma unroll
                for (int j = 0; j < 8; j++) {
                    float v = fmaxf(acc[i][j] + bv[j], 0.f);
                    __nv_bfloat16 h = __float2bfloat16(v);
                    hi8[j] = h;
                    lo8[j] = __float2bfloat16(v - __bfloat162float(h));
                }
                *(uint4*)&g_headH[(size_t)row * HSZ + tx * 8] = *(uint4*)hi8;
                *(uint4*)&g_headL[(size_t)row * HSZ + tx * 8] = *(uint4*)lo8;
            } else {
                float o[8];
#pragma unroll
                for (int j = 0; j < 8; j++) o[j] = fmaxf(acc[i][j] + bv[j], 0.f);
                *(float4*)&g_tail[(size_t)row * HSZ + tx * 8]     = *(float4*)&o[0];
                *(float4*)&g_tail[(size_t)row * HSZ + tx * 8 + 4] = *(float4*)&o[4];
            }
        }
    }
}

// ---------------------------------------------------------------------------
// Kernel 2: biaffine via mma.sync bf16 (3-pass split precision).
//   CTA = 128 tokens x 1 r. 8 warps, warp tile 64(M) x 32(N).
//   smem: Ah|Al|Bh|Bl as 128 x 136 bf16 (272B padded rows, ldmatrix-safe)
//         + red[128] fp32 token accumulators.
//   Epilogue: acc(t,k) * tail(t,k) fragment dot, quad shfl-reduce,
//             shared atomicAdd, then one store per token.
// ---------------------------------------------------------------------------
#define APITCH 136                          // bf16 elems per padded row (272 B)
#define TILE_B (128 * APITCH * 2)           // 34816 bytes per tile

__global__ __launch_bounds__(256) void biaffine_mma(
    const int* __restrict__ head_id,
    float* __restrict__ out)
{
    extern __shared__ char smem[];
    const uint32_t sb  = smem_u32(smem);
    const uint32_t Ah_u = sb;
    const uint32_t Al_u = sb + TILE_B;
    const uint32_t Bh_u = sb + 2 * TILE_B;
    const uint32_t Bl_u = sb + 3 * TILE_B;
    float* red = (float*)(smem + 4 * TILE_B);

    const int r   = blockIdx.x;
    const int t0  = blockIdx.y * 128;
    const int tid = threadIdx.x;
    const int lane = tid & 31;
    const int warp = tid >> 5;
    const int wm = warp >> 2;              // 0..1 (M)
    const int wn = warp & 3;               // 0..3 (N)

    // --- async loads: B tiles (dense [n][k] -> padded) ---
    {
        const __nv_bfloat16* srcH = g_KH + (size_t)r * HSZ * HSZ;
        const __nv_bfloat16* srcL = g_KL + (size_t)r * HSZ * HSZ;
#pragma unroll
        for (int i = 0; i < 8; i++) {
            int c   = tid + i * 256;       // 0..2047
            int row = c >> 4;
            int col = c & 15;              // 16B chunk
            uint32_t so = (uint32_t)row * (APITCH * 2) + col * 16;
            CP16(Bh_u + so, srcH + (size_t)row * HSZ + col * 8);
            CP16(Bl_u + so, srcL + (size_t)row * HSZ + col * 8);
        }
    }
    // --- async loads: A tiles (gathered head rows) ---
    {
#pragma unroll
        for (int i = 0; i < 8; i++) {
            int c   = tid + i * 256;
            int row = c >> 4;
            int col = c & 15;
            int t   = t0 + row;
            int hid = head_id[t];
            size_t base = ((size_t)(t >> 10) * APP + hid) * HSZ;
            uint32_t so = (uint32_t)row * (APITCH * 2) + col * 16;
            CP16(Ah_u + so, g_headH + base + col * 8);
            CP16(Al_u + so, g_headL + base + col * 8);
        }
    }
    if (tid < 128) red[tid] = 0.f;
    CP_COMMIT();
    CP_WAIT0();
    __syncthreads();

    // --- 3-pass HMMA: Ah*Bh, Al*Bh, Ah*Bl ---
    float acc[4][4][4];
#pragma unroll
    for (int mt = 0; mt < 4; mt++)
#pragma unroll
        for (int nt = 0; nt < 4; nt++)
#pragma unroll
            for (int e = 0; e < 4; e++) acc[mt][nt][e] = 0.f;

    const uint32_t aLaneOff = (uint32_t)(wm * 64 + (lane & 15)) * (APITCH * 2)
                            + (uint32_t)(lane >> 4) * 16;
    const uint32_t bLaneOff = (uint32_t)(wn * 32 + (lane & 7) + ((lane >> 4) << 3)) * (APITCH * 2)
                            + (uint32_t)((lane >> 3) & 1) * 16;

#pragma unroll
    for (int pass = 0; pass < 3; pass++) {
        const uint32_t aBase = ((pass == 1) ? Al_u : Ah_u) + aLaneOff;
        const uint32_t bBase = ((pass == 2) ? Bl_u : Bh_u) + bLaneOff;
#pragma unroll
        for (int k = 0; k < 8; k++) {
            uint32_t aF[4][4];
#pragma unroll
            for (int mt = 0; mt < 4; mt++)
                LDMX4(aF[mt], aBase + (uint32_t)mt * 16 * (APITCH * 2) + (uint32_t)k * 32);
            uint32_t bF[2][4];
#pragma unroll
            for (int np = 0; np < 2; np++)
                LDMX4(bF[np], bBase + (uint32_t)np * 16 * (APITCH * 2) + (uint32_t)k * 32);
#pragma unroll
            for (int mt = 0; mt < 4; mt++)
#pragma unroll
                for (int nt = 0; nt < 4; nt++)
                    MMA16816(acc[mt][nt], aF[mt],
                             bF[nt >> 1][(nt & 1) * 2], bF[nt >> 1][(nt & 1) * 2 + 1]);
        }
    }

    // --- fused epilogue: out[t,r] = sum_k P[t,k]*tail[t,k] ---
#pragma unroll
    for (int mt = 0; mt < 4; mt++) {
#pragma unroll
        for (int half = 0; half < 2; half++) {
            const int lrow = wm * 64 + mt * 16 + (lane >> 2) + half * 8;
            const int t    = t0 + lrow;
            float p = 0.f;
#pragma unroll
            for (int nt = 0; nt < 4; nt++) {
                const int col = wn * 32 + nt * 8 + (lane & 3) * 2;
                float2 tl = *(const float2*)&g_tail[(size_t)t * HSZ + col];
                p += acc[mt][nt][half * 2 + 0] * tl.x
                   + acc[mt][nt][half * 2 + 1] * tl.y;
            }
            p += __shfl_xor_sync(0xffffffffu, p, 1);
            p += __shfl_xor_sync(0xffffffffu, p, 2);
            if ((lane & 3) == 0) atomicAdd(&red[lrow], p);
        }
    }
    __syncthreads();
    if (tid < 128)
        out[(size_t)(t0 + tid) * RSZ + r] = red[tid];
}

// ---------------------------------------------------------------------------
extern "C" void kernel_launch(void* const* d_in, const int* in_sizes, int n_in,
                              void* d_out, int out_size)
{
    const float* x       = (const float*)d_in[0];
    const int*   head_id = (const int*)  d_in[1];
    const float* root    = (const float*)d_in[2];
    const float* Wh      = (const float*)d_in[3];
    const float* bh      = (const float*)d_in[4];
    const float* Wt      = (const float*)d_in[5];
    const float* bt      = (const float*)d_in[6];
    const float* Kmat    = (const float*)d_in[7];
    float*       out     = (float*)d_out;

    prep_kernel<<<RSZ, 256>>>(Kmat);
    ff_kernel<<<dim3(257, 2), 256>>>(x, root, Wh, bh, Wt, bt);

    const int smem_bytes = 4 * TILE_B + 128 * sizeof(float);   // 139776 + 512
    cudaFuncSetAttribute(biaffine_mma,
                         cudaFuncAttributeMaxDynamicSharedMemorySize, smem_bytes);
    biaffine_mma<<<dim3(RSZ, NTOK / 128), 256, smem_bytes>>>(head_id, out);
}

// round 4
// speedup vs baseline: 2.9689x; 1.3517x over previous
#include <cuda_runtime.h>
#include <cuda_bf16.h>
#include <cstdint>

// Problem constants
#define BSZ   32
#define SSZ   1024
#define DSZ   768
#define HSZ   128
#define RSZ   48
#define APP   (SSZ + 1)        // 1025
#define NTOK  (BSZ * SSZ)      // 32768
#define MHEAD (BSZ * APP)      // 32800

// Scratch (device globals)
__device__ __nv_bfloat16 g_headH[(size_t)MHEAD * HSZ];
__device__ __nv_bfloat16 g_headL[(size_t)MHEAD * HSZ];
__device__ float         g_tail [(size_t)NTOK * HSZ];
__device__ __nv_bfloat16 g_KH[(size_t)RSZ * HSZ * HSZ];   // B_r[n][h] hi
__device__ __nv_bfloat16 g_KL[(size_t)RSZ * HSZ * HSZ];   // B_r[n][h] lo
__device__ __nv_bfloat16 g_WH[(size_t)2 * HSZ * DSZ];     // W^T [branch][n][k] hi
__device__ __nv_bfloat16 g_WL[(size_t)2 * HSZ * DSZ];     // W^T [branch][n][k] lo

// ---------------------------------------------------------------------------
// PTX helpers (target-suffix-free)
// ---------------------------------------------------------------------------
__device__ __forceinline__ uint32_t smem_u32(const void* p) {
    uint32_t a;
    asm("{ .reg .u64 t; cvta.to.shared.u64 t, %1; cvt.u32.u64 %0, t; }" : "=r"(a) : "l"(p));
    return a;
}

#define CP16(dst, src) \
    asm volatile("cp.async.cg.shared.global [%0], [%1], 16;" :: "r"(dst), "l"(src) : "memory")
#define CP_COMMIT() asm volatile("cp.async.commit_group;" ::: "memory")
#define CP_WAIT0()  asm volatile("cp.async.wait_group 0;" ::: "memory")
#define CP_WAIT1()  asm volatile("cp.async.wait_group 1;" ::: "memory")

#define LDMX4(r, addr) \
    asm volatile("ldmatrix.sync.aligned.m8n8.x4.shared.b16 {%0,%1,%2,%3}, [%4];" \
        : "=r"((r)[0]), "=r"((r)[1]), "=r"((r)[2]), "=r"((r)[3]) : "r"(addr))

#define MMA16816(c, a, b0, b1) \
    asm volatile("mma.sync.aligned.m16n8k16.row.col.f32.bf16.bf16.f32 " \
        "{%0,%1,%2,%3}, {%4,%5,%6,%7}, {%8,%9}, {%0,%1,%2,%3};" \
        : "+f"((c)[0]), "+f"((c)[1]), "+f"((c)[2]), "+f"((c)[3]) \
        : "r"((a)[0]), "r"((a)[1]), "r"((a)[2]), "r"((a)[3]), "r"(b0), "r"(b1))

__device__ __forceinline__ void split_bf16(float v, __nv_bfloat16& hi, __nv_bfloat16& lo) {
    hi = __float2bfloat16(v);
    lo = __float2bfloat16(v - __bfloat162float(hi));
}

// ---------------------------------------------------------------------------
// Kernel 0a: prep K — smem-tiled transpose + hi/lo split. Coalesced both ways.
// ---------------------------------------------------------------------------
__global__ __launch_bounds__(256) void prep_k(const float* __restrict__ Kmat)
{
    __shared__ float ts[128 * 33];
    const int r  = blockIdx.x;
    const int nb = blockIdx.y;                 // 32 n per block
    const int tid = threadIdx.x;
#pragma unroll
    for (int j = 0; j < 16; j++) {
        int idx = tid + j * 256;               // 4096
        int h  = idx >> 5;
        int nc = idx & 31;
        ts[h * 33 + nc] = Kmat[(size_t)h * (HSZ * RSZ) + r * HSZ + nb * 32 + nc];
    }
    __syncthreads();
#pragma unroll
    for (int j = 0; j < 16; j++) {
        int idx = tid + j * 256;
        int nc = idx >> 7;
        int h  = idx & 127;
        float v = ts[h * 33 + nc];
        __nv_bfloat16 hi, lo; split_bf16(v, hi, lo);
        size_t off = (size_t)r * HSZ * HSZ + (size_t)(nb * 32 + nc) * HSZ + h;
        g_KH[off] = hi;
        g_KL[off] = lo;
    }
}

// ---------------------------------------------------------------------------
// Kernel 0b: prep W — transpose Wh/Wt (768x128 -> [n][k]) + hi/lo split.
// ---------------------------------------------------------------------------
__global__ __launch_bounds__(256) void prep_w(const float* __restrict__ Wh,
                                              const float* __restrict__ Wt)
{
    __shared__ float tw[32 * 129];
    const int kb = blockIdx.x;                 // 32 k-rows per block (24 blocks)
    const int br = blockIdx.y;
    const float* W = br ? Wt : Wh;
    const int tid = threadIdx.x;
#pragma unroll
    for (int j = 0; j < 16; j++) {
        int idx = tid + j * 256;
        int k = idx >> 7;
        int n = idx & 127;
        tw[k * 129 + n] = W[(size_t)(kb * 32 + k) * HSZ + n];
    }
    __syncthreads();
#pragma unroll
    for (int j = 0; j < 16; j++) {
        int idx = tid + j * 256;
        int n = idx >> 5;
        int k = idx & 31;
        float v = tw[k * 129 + n];
        __nv_bfloat16 hi, lo; split_bf16(v, hi, lo);
        size_t off = (size_t)br * HSZ * DSZ + (size_t)n * DSZ + kb * 32 + k;
        g_WH[off] = hi;
        g_WL[off] = lo;
    }
}

// ---------------------------------------------------------------------------
// Kernel 1: dual FF GEMM on tensor cores (3-pass split bf16).
//   CTA = 128 rows x 128 cols, K=768 in 24 chunks of 32, 2-stage pipeline.
//   A: gathered x/root rows, fp32 LDG -> hi/lo bf16 STS (single buffer).
//   B: pre-split W^T, cp.async double buffer.
// smem rows padded to 40 bf16 (80B) -> ldmatrix conflict-free.
// ---------------------------------------------------------------------------
#define FFP   40                                   // bf16 pitch
#define FFROW 80                                   // bytes per row
#define FF_AT (128 * FFROW)                        // 10240 per matrix
#define FF_AH 0
#define FF_AL FF_AT
#define FF_BB (2 * FF_AT)                          // B buffers start
#define FF_BS (2 * FF_AT)                          // per-buffer (hi+lo)
#define FF_SMEM (FF_BB + 2 * FF_BS)                // 61440

__global__ __launch_bounds__(256) void ff_mma(
    const float* __restrict__ x,
    const float* __restrict__ root,
    const float* __restrict__ bh, const float* __restrict__ bt)
{
    extern __shared__ char sm[];
    const uint32_t sb = smem_u32(sm);

    const int branch = blockIdx.y;
    const int M      = (branch == 0) ? MHEAD : NTOK;
    const int m0     = blockIdx.x * 128;
    if (m0 >= M) return;

    const float* bias = (branch == 0) ? bh : bt;
    const __nv_bfloat16* WH = g_WH + (size_t)branch * HSZ * DSZ;
    const __nv_bfloat16* WL = g_WL + (size_t)branch * HSZ * DSZ;

    const int tid  = threadIdx.x;
    const int lane = tid & 31;
    const int warp = tid >> 5;
    const int wm   = warp >> 2;
    const int wn   = warp & 3;

    // per-thread A rows (4 float4 per chunk)
    const float* arow[4];
    bool rowok[4];
    int rown[4], colf[4];
#pragma unroll
    for (int i = 0; i < 4; i++) {
        int c   = tid + i * 256;
        int row = c >> 3;
        int c4  = c & 7;
        rown[i] = row; colf[i] = c4;
        int g = m0 + row;
        const float* p = nullptr;
        bool ok = (g < M);
        if (ok) {
            if (branch == 0) {
                int b  = g / APP;
                int ii = g - b * APP;
                p = (ii == 0) ? root : (x + (size_t)(b * SSZ + (ii - 1)) * DSZ);
            } else {
                p = x + (size_t)g * DSZ;
            }
        }
        arow[i] = p; rowok[i] = ok;
    }

    // B prefetch helper (512 x 16B per matrix, 2 per thread each)
    auto load_B = [&](uint32_t buf, int k0) {
#pragma unroll
        for (int i = 0; i < 2; i++) {
            int c   = tid + i * 256;      // 0..511
            int row = c >> 2;
            int c4  = c & 3;
            size_t so = (size_t)row * DSZ + k0 + c4 * 8;
            uint32_t d = buf + row * FFROW + c4 * 16;
            CP16(d, WH + so);
            CP16(d + FF_BS / 2, WL + so);
        }
    };

    // prologue: A chunk0 regs + B chunk0 cp.async
    float4 va[4];
#pragma unroll
    for (int i = 0; i < 4; i++)
        va[i] = rowok[i] ? *(const float4*)(arow[i] + colf[i] * 4)
                         : make_float4(0.f, 0.f, 0.f, 0.f);
    load_B(sb + FF_BB, 0);
    CP_COMMIT();

    float acc[4][4][4];
#pragma unroll
    for (int mt = 0; mt < 4; mt++)
#pragma unroll
        for (int nt = 0; nt < 4; nt++)
#pragma unroll
            for (int e = 0; e < 4; e++) acc[mt][nt][e] = 0.f;

    const uint32_t aLaneOff = (uint32_t)(wm * 64 + (lane & 15)) * FFROW
                            + (uint32_t)(lane >> 4) * 16;
    const uint32_t bLaneOff = (uint32_t)(wn * 32 + (lane & 7) + ((lane >> 4) << 3)) * FFROW
                            + (uint32_t)((lane >> 3) & 1) * 16;

#pragma unroll 1
    for (int ch = 0; ch < 24; ch++) {
        const int nxt = ch + 1;
        if (nxt < 24) load_B(sb + FF_BB + (nxt & 1) * FF_BS, nxt * 32);
        CP_COMMIT();

        // convert + STS A chunk ch
#pragma unroll
        for (int i = 0; i < 4; i++) {
            __nv_bfloat16 h0, h1, h2, h3, l0, l1, l2, l3;
            split_bf16(va[i].x, h0, l0); split_bf16(va[i].y, h1, l1);
            split_bf16(va[i].z, h2, l2); split_bf16(va[i].w, h3, l3);
            uint32_t hw0 = (uint32_t)__bfloat16_as_ushort(h0) | ((uint32_t)__bfloat16_as_ushort(h1) << 16);
            uint32_t hw1 = (uint32_t)__bfloat16_as_ushort(h2) | ((uint32_t)__bfloat16_as_ushort(h3) << 16);
            uint32_t lw0 = (uint32_t)__bfloat16_as_ushort(l0) | ((uint32_t)__bfloat16_as_ushort(l1) << 16);
            uint32_t lw1 = (uint32_t)__bfloat16_as_ushort(l2) | ((uint32_t)__bfloat16_as_ushort(l3) << 16);
            uint32_t off = rown[i] * FFROW + colf[i] * 8;
            *(uint2*)(sm + FF_AH + off) = make_uint2(hw0, hw1);
            *(uint2*)(sm + FF_AL + off) = make_uint2(lw0, lw1);
        }
        // prefetch next A chunk
        if (nxt < 24) {
#pragma unroll
            for (int i = 0; i < 4; i++)
                va[i] = rowok[i] ? *(const float4*)(arow[i] + nxt * 32 + colf[i] * 4)
                                 : make_float4(0.f, 0.f, 0.f, 0.f);
        }
        CP_WAIT1();
        __syncthreads();

        const uint32_t bufb = sb + FF_BB + (ch & 1) * FF_BS;
#pragma unroll
        for (int pass = 0; pass < 3; pass++) {
            const uint32_t aB = sb + ((pass == 1) ? FF_AL : FF_AH) + aLaneOff;
            const uint32_t bB = bufb + ((pass == 2) ? (FF_BS / 2) : 0) + bLaneOff;
#pragma unroll
            for (int ks = 0; ks < 2; ks++) {
                uint32_t aF[4][4];
#pragma unroll
                for (int mt = 0; mt < 4; mt++)
                    LDMX4(aF[mt], aB + (uint32_t)mt * 16 * FFROW + (uint32_t)ks * 32);
                uint32_t bF[2][4];
#pragma unroll
                for (int np = 0; np < 2; np++)
                    LDMX4(bF[np], bB + (uint32_t)np * 16 * FFROW + (uint32_t)ks * 32);
#pragma unroll
                for (int mt = 0; mt < 4; mt++)
#pragma unroll
                    for (int nt = 0; nt < 4; nt++)
                        MMA16816(acc[mt][nt], aF[mt],
                                 bF[nt >> 1][(nt & 1) * 2], bF[nt >> 1][(nt & 1) * 2 + 1]);
            }
        }
        __syncthreads();
    }

    // epilogue: bias + relu + store (branch0: hi/lo bf16; branch1: fp32)
    float2 bv[4];
#pragma unroll
    for (int nt = 0; nt < 4; nt++)
        bv[nt] = *(const float2*)&bias[wn * 32 + nt * 8 + (lane & 3) * 2];

#pragma unroll
    for (int mt = 0; mt < 4; mt++) {
#pragma unroll
        for (int half = 0; half < 2; half++) {
            const int row  = wm * 64 + mt * 16 + (lane >> 2) + half * 8;
            const int grow = m0 + row;
            if (grow >= M) continue;
#pragma unroll
            for (int nt = 0; nt < 4; nt++) {
                const int col = wn * 32 + nt * 8 + (lane & 3) * 2;
                float f0 = fmaxf(acc[mt][nt][half * 2 + 0] + bv[nt].x, 0.f);
                float f1 = fmaxf(acc[mt][nt][half * 2 + 1] + bv[nt].y, 0.f);
                if (branch == 0) {
                    __nv_bfloat16 h0, l0, h1, l1;
                    split_bf16(f0, h0, l0); split_bf16(f1, h1, l1);
                    *(uint32_t*)&g_headH[(size_t)grow * HSZ + col] =
                        (uint32_t)__bfloat16_as_ushort(h0) | ((uint32_t)__bfloat16_as_ushort(h1) << 16);
                    *(uint32_t*)&g_headL[(size_t)grow * HSZ + col] =
                        (uint32_t)__bfloat16_as_ushort(l0) | ((uint32_t)__bfloat16_as_ushort(l1) << 16);
                } else {
                    *(float2*)&g_tail[(size_t)grow * HSZ + col] = make_float2(f0, f1);
                }
            }
        }
    }
}

// ---------------------------------------------------------------------------
// Kernel 2: biaffine, 128 tokens x 4 r per CTA.
//   A (head hi/lo) resident; B (K images) double-buffered cp.async pipeline.
//   red[128][4] accumulators -> one float4 store per token.
// ---------------------------------------------------------------------------
#define APITCH 136
#define TILE_B (128 * APITCH * 2)      // 34816
#define BI_AH 0
#define BI_AL TILE_B
#define BI_BB (2 * TILE_B)             // 69632
#define BI_BS (2 * TILE_B)             // per buffer (Bh+Bl)
#define BI_RED (BI_BB + 2 * BI_BS)     // 208896
#define BI_SMEM (BI_RED + 128 * 4 * 4) // 210944

__global__ __launch_bounds__(256) void biaffine_mma(
    const int* __restrict__ head_id,
    float* __restrict__ out)
{
    extern __shared__ char sm[];
    const uint32_t sb = smem_u32(sm);
    float* red = (float*)(sm + BI_RED);

    const int rg  = blockIdx.x;            // r group: r = rg*4 + i
    const int t0  = blockIdx.y * 128;
    const int tid = threadIdx.x;
    const int lane = tid & 31;
    const int warp = tid >> 5;
    const int wm = warp >> 2;
    const int wn = warp & 3;

    auto load_B = [&](uint32_t buf, int r) {
        const __nv_bfloat16* srcH = g_KH + (size_t)r * HSZ * HSZ;
        const __nv_bfloat16* srcL = g_KL + (size_t)r * HSZ * HSZ;
#pragma unroll
        for (int i = 0; i < 8; i++) {
            int c   = tid + i * 256;
            int row = c >> 4;
            int col = c & 15;
            uint32_t so = (uint32_t)row * (APITCH * 2) + col * 16;
            size_t go = (size_t)row * HSZ + col * 8;
            CP16(buf + so, srcH + go);
            CP16(buf + TILE_B + so, srcL + go);
        }
    };

    // prologue: A gather + B(r0) + red zero
    {
#pragma unroll
        for (int i = 0; i < 8; i++) {
            int c   = tid + i * 256;
            int row = c >> 4;
            int col = c & 15;
            int t   = t0 + row;
            int hid = head_id[t];
            size_t base = ((size_t)(t >> 10) * APP + hid) * HSZ + col * 8;
            uint32_t so = (uint32_t)row * (APITCH * 2) + col * 16;
            CP16(sb + BI_AH + so, g_headH + base);
            CP16(sb + BI_AL + so, g_headL + base);
        }
        load_B(sb + BI_BB, rg * 4);
        if (tid < 128) *(float4*)&red[tid * 4] = make_float4(0.f, 0.f, 0.f, 0.f);
        CP_COMMIT();
    }

    const uint32_t aLaneOff = (uint32_t)(wm * 64 + (lane & 15)) * (APITCH * 2)
                            + (uint32_t)(lane >> 4) * 16;
    const uint32_t bLaneOff = (uint32_t)(wn * 32 + (lane & 7) + ((lane >> 4) << 3)) * (APITCH * 2)
                            + (uint32_t)((lane >> 3) & 1) * 16;

#pragma unroll 1
    for (int i = 0; i < 4; i++) {
        if (i < 3) load_B(sb + BI_BB + ((i + 1) & 1) * BI_BS, rg * 4 + i + 1);
        CP_COMMIT();
        CP_WAIT1();
        __syncthreads();

        float acc[4][4][4];
#pragma unroll
        for (int mt = 0; mt < 4; mt++)
#pragma unroll
            for (int nt = 0; nt < 4; nt++)
#pragma unroll
                for (int e = 0; e < 4; e++) acc[mt][nt][e] = 0.f;

        const uint32_t bufb = sb + BI_BB + (i & 1) * BI_BS;
#pragma unroll
        for (int pass = 0; pass < 3; pass++) {
            const uint32_t aB = sb + ((pass == 1) ? BI_AL : BI_AH) + aLaneOff;
            const uint32_t bB = bufb + ((pass == 2) ? TILE_B : 0) + bLaneOff;
#pragma unroll
            for (int k = 0; k < 8; k++) {
                uint32_t aF[4][4];
#pragma unroll
                for (int mt = 0; mt < 4; mt++)
                    LDMX4(aF[mt], aB + (uint32_t)mt * 16 * (APITCH * 2) + (uint32_t)k * 32);
                uint32_t bF[2][4];
#pragma unroll
                for (int np = 0; np < 2; np++)
                    LDMX4(bF[np], bB + (uint32_t)np * 16 * (APITCH * 2) + (uint32_t)k * 32);
#pragma unroll
                for (int mt = 0; mt < 4; mt++)
#pragma unroll
                    for (int nt = 0; nt < 4; nt++)
                        MMA16816(acc[mt][nt], aF[mt],
                                 bF[nt >> 1][(nt & 1) * 2], bF[nt >> 1][(nt & 1) * 2 + 1]);
            }
        }

        // epilogue: dot with tail, quad-reduce, accumulate into red[:,i]
#pragma unroll
        for (int mt = 0; mt < 4; mt++) {
#pragma unroll
            for (int half = 0; half < 2; half++) {
                const int lrow = wm * 64 + mt * 16 + (lane >> 2) + half * 8;
                const int t    = t0 + lrow;
                float p = 0.f;
#pragma unroll
                for (int nt = 0; nt < 4; nt++) {
                    const int col = wn * 32 + nt * 8 + (lane & 3) * 2;
                    float2 tl = *(const float2*)&g_tail[(size_t)t * HSZ + col];
                    p += acc[mt][nt][half * 2 + 0] * tl.x
                       + acc[mt][nt][half * 2 + 1] * tl.y;
                }
                p += __shfl_xor_sync(0xffffffffu, p, 1);
                p += __shfl_xor_sync(0xffffffffu, p, 2);
                if ((lane & 3) == 0) atomicAdd(&red[lrow * 4 + i], p);
            }
        }
        __syncthreads();
    }

    if (tid < 128) {
        float4 v = *(float4*)&red[tid * 4];
        *(float4*)&out[(size_t)(t0 + tid) * RSZ + rg * 4] = v;
    }
}

// ---------------------------------------------------------------------------
extern "C" void kernel_launch(void* const* d_in, const int* in_sizes, int n_in,
                              void* d_out, int out_size)
{
    const float* x       = (const float*)d_in[0];
    const int*   head_id = (const int*)  d_in[1];
    const float* root    = (const float*)d_in[2];
    const float* Wh      = (const float*)d_in[3];
    const float* bh      = (const float*)d_in[4];
    const float* Wt      = (const float*)d_in[5];
    const float* bt      = (const float*)d_in[6];
    const float* Kmat    = (const float*)d_in[7];
    float*       out     = (float*)d_out;

    prep_k<<<dim3(RSZ, 4), 256>>>(Kmat);
    prep_w<<<dim3(24, 2), 256>>>(Wh, Wt);

    cudaFuncSetAttribute(ff_mma, cudaFuncAttributeMaxDynamicSharedMemorySize, FF_SMEM);
    ff_mma<<<dim3(257, 2), 256, FF_SMEM>>>(x, root, bh, bt);

    cudaFuncSetAttribute(biaffine_mma, cudaFuncAttributeMaxDynamicSharedMemorySize, BI_SMEM);
    biaffine_mma<<<dim3(RSZ / 4, NTOK / 128), 256, BI_SMEM>>>(head_id, out);
}